// round 1
// baseline (speedup 1.0000x reference)
#include <cuda_runtime.h>
#include <math.h>

#define N_TOK 4096
#define H_DIM 1024
#define F_DIM 4096
#define N_EXP 8

#define BM 128
#define BN 128
#define BK 8
#define TM 8
#define TN 8
#define NTHREADS 256
#define TILES_PER_E (N_TOK / BM)  // 32

// Routing state + h scratch (allocation-free: __device__ globals).
__device__ int   g_cnt[N_EXP];
__device__ int   g_off[N_EXP];
__device__ int   g_tok[N_EXP * N_TOK];
__device__ float g_gw [N_EXP * N_TOK];
// Compact padded capacity: 8192 rows + 8*127 pad <= 9216 rows.
__device__ float g_h[(size_t)9216 * F_DIM];

__global__ void zero_kernel(float* __restrict__ out, int n) {
    int i = blockIdx.x * blockDim.x + threadIdx.x;
    if (i < N_EXP) g_cnt[i] = 0;
    int stride = gridDim.x * blockDim.x;
    for (int j = i; j < n; j += stride) out[j] = 0.0f;
}

__global__ void gate_kernel(const float* __restrict__ x,
                            const float* __restrict__ Wg,
                            const float* __restrict__ bg) {
    int warp = threadIdx.x >> 5;
    int lane = threadIdx.x & 31;
    int n = blockIdx.x * (blockDim.x >> 5) + warp;
    if (n >= N_TOK) return;

    float acc[N_EXP];
#pragma unroll
    for (int e = 0; e < N_EXP; e++) acc[e] = 0.0f;

    const float* xr = x + (size_t)n * H_DIM;
    for (int h = lane; h < H_DIM; h += 32) {
        float xv = xr[h];
        const float4 w0 = *reinterpret_cast<const float4*>(Wg + h * N_EXP);
        const float4 w1 = *reinterpret_cast<const float4*>(Wg + h * N_EXP + 4);
        acc[0] += xv * w0.x; acc[1] += xv * w0.y;
        acc[2] += xv * w0.z; acc[3] += xv * w0.w;
        acc[4] += xv * w1.x; acc[5] += xv * w1.y;
        acc[6] += xv * w1.z; acc[7] += xv * w1.w;
    }
#pragma unroll
    for (int e = 0; e < N_EXP; e++) {
#pragma unroll
        for (int o = 16; o > 0; o >>= 1)
            acc[e] += __shfl_xor_sync(0xffffffffu, acc[e], o);
    }

    if (lane == 0) {
        float lg[N_EXP];
        float m = -1e30f;
#pragma unroll
        for (int e = 0; e < N_EXP; e++) {
            lg[e] = acc[e] + bg[e];
            m = fmaxf(m, lg[e]);
        }
        float s = 0.0f;
        float p[N_EXP];
#pragma unroll
        for (int e = 0; e < N_EXP; e++) { p[e] = expf(lg[e] - m); s += p[e]; }
        float inv = 1.0f / s;
#pragma unroll
        for (int e = 0; e < N_EXP; e++) p[e] *= inv;

        // stable top-2 (ties -> lower index, matching jax.lax.top_k)
        int i0 = 0;
#pragma unroll
        for (int e = 1; e < N_EXP; e++) if (p[e] > p[i0]) i0 = e;
        int i1 = (i0 == 0) ? 1 : 0;
#pragma unroll
        for (int e = 0; e < N_EXP; e++) {
            if (e != i0 && p[e] > p[i1]) i1 = e;
        }

        int pos0 = atomicAdd(&g_cnt[i0], 1);
        g_tok[i0 * N_TOK + pos0] = n;
        g_gw [i0 * N_TOK + pos0] = p[i0];
        int pos1 = atomicAdd(&g_cnt[i1], 1);
        g_tok[i1 * N_TOK + pos1] = n;
        g_gw [i1 * N_TOK + pos1] = p[i1];
    }
}

__global__ void offsets_kernel() {
    if (threadIdx.x == 0 && blockIdx.x == 0) {
        int off = 0;
        for (int e = 0; e < N_EXP; e++) {
            g_off[e] = off;
            off += ((g_cnt[e] + BM - 1) / BM) * BM;
        }
    }
}

// h = gelu(X_gathered @ W1[e] + b1[e])  -> g_h scratch
__global__ __launch_bounds__(NTHREADS) void ffn1_kernel(
    const float* __restrict__ x,
    const float* __restrict__ W1,
    const float* __restrict__ b1) {
    int e    = blockIdx.y / TILES_PER_E;
    int tile = blockIdx.y % TILES_PER_E;
    int row0 = tile * BM;
    int cnt  = g_cnt[e];
    if (row0 >= cnt) return;
    int off  = g_off[e];
    int col0 = blockIdx.x * BN;
    const float* B = W1 + (size_t)e * H_DIM * F_DIM;   // [H, F]

    __shared__ float As[BK][BM];
    __shared__ float Bs[BK][BN];
    __shared__ int   toks[BM];

    int tid = threadIdx.x;
    if (tid < BM) {
        int r = row0 + tid;
        if (r >= cnt) r = cnt - 1;   // clamp: padded rows compute a valid token, discarded later
        toks[tid] = g_tok[e * N_TOK + r];
    }
    __syncthreads();

    int tx = tid & 15;
    int ty = tid >> 4;
    float acc[TM][TN];
#pragma unroll
    for (int i = 0; i < TM; i++)
#pragma unroll
        for (int j = 0; j < TN; j++) acc[i][j] = 0.0f;

    int ar_row = tid >> 1;
    int ar_seg = (tid & 1) * 4;
    int bs_row = tid >> 5;
    int bs_col = (tid & 31) * 4;
    const float* a_base = x + (size_t)toks[ar_row] * H_DIM + ar_seg;

    for (int k0 = 0; k0 < H_DIM; k0 += BK) {
        float4 av = *reinterpret_cast<const float4*>(a_base + k0);
        float4 bv = *reinterpret_cast<const float4*>(B + (size_t)(k0 + bs_row) * F_DIM + col0 + bs_col);
        As[ar_seg + 0][ar_row] = av.x;
        As[ar_seg + 1][ar_row] = av.y;
        As[ar_seg + 2][ar_row] = av.z;
        As[ar_seg + 3][ar_row] = av.w;
        *reinterpret_cast<float4*>(&Bs[bs_row][bs_col]) = bv;
        __syncthreads();
#pragma unroll
        for (int kk = 0; kk < BK; kk++) {
            float ar[TM], br[TN];
#pragma unroll
            for (int i = 0; i < TM; i++) ar[i] = As[kk][ty * TM + i];
#pragma unroll
            for (int j = 0; j < TN; j++) br[j] = Bs[kk][tx * TN + j];
#pragma unroll
            for (int i = 0; i < TM; i++)
#pragma unroll
                for (int j = 0; j < TN; j++) acc[i][j] += ar[i] * br[j];
        }
        __syncthreads();
    }

#pragma unroll
    for (int i = 0; i < TM; i++) {
        int r = row0 + ty * TM + i;
        float* hrow = g_h + (size_t)(off + r) * F_DIM + col0 + tx * TN;
#pragma unroll
        for (int j = 0; j < TN; j++) {
            float v = acc[i][j] + b1[e * F_DIM + col0 + tx * TN + j];
            hrow[j] = 0.5f * v * (1.0f + erff(v * 0.70710678118654752f));
        }
    }
}

// out[token] += gw * (h @ W2[e] + b2[e])
__global__ __launch_bounds__(NTHREADS) void ffn2_kernel(
    const float* __restrict__ W2,
    const float* __restrict__ b2,
    float* __restrict__ out) {
    int e    = blockIdx.y / TILES_PER_E;
    int tile = blockIdx.y % TILES_PER_E;
    int row0 = tile * BM;
    int cnt  = g_cnt[e];
    if (row0 >= cnt) return;
    int off  = g_off[e];
    int col0 = blockIdx.x * BN;
    const float* B = W2 + (size_t)e * F_DIM * H_DIM;   // [F, H]
    const float* A = g_h + (size_t)off * F_DIM;

    __shared__ float As[BK][BM];
    __shared__ float Bs[BK][BN];

    int tid = threadIdx.x;
    int tx = tid & 15;
    int ty = tid >> 4;
    float acc[TM][TN];
#pragma unroll
    for (int i = 0; i < TM; i++)
#pragma unroll
        for (int j = 0; j < TN; j++) acc[i][j] = 0.0f;

    int ar_row = tid >> 1;
    int ar_seg = (tid & 1) * 4;
    int bs_row = tid >> 5;
    int bs_col = (tid & 31) * 4;
    const float* a_base = A + (size_t)(row0 + ar_row) * F_DIM + ar_seg;

    for (int k0 = 0; k0 < F_DIM; k0 += BK) {
        float4 av = *reinterpret_cast<const float4*>(a_base + k0);
        float4 bv = *reinterpret_cast<const float4*>(B + (size_t)(k0 + bs_row) * H_DIM + col0 + bs_col);
        As[ar_seg + 0][ar_row] = av.x;
        As[ar_seg + 1][ar_row] = av.y;
        As[ar_seg + 2][ar_row] = av.z;
        As[ar_seg + 3][ar_row] = av.w;
        *reinterpret_cast<float4*>(&Bs[bs_row][bs_col]) = bv;
        __syncthreads();
#pragma unroll
        for (int kk = 0; kk < BK; kk++) {
            float ar[TM], br[TN];
#pragma unroll
            for (int i = 0; i < TM; i++) ar[i] = As[kk][ty * TM + i];
#pragma unroll
            for (int j = 0; j < TN; j++) br[j] = Bs[kk][tx * TN + j];
#pragma unroll
            for (int i = 0; i < TM; i++)
#pragma unroll
                for (int j = 0; j < TN; j++) acc[i][j] += ar[i] * br[j];
        }
        __syncthreads();
    }

#pragma unroll
    for (int i = 0; i < TM; i++) {
        int r = row0 + ty * TM + i;
        if (r < cnt) {
            int   token = g_tok[e * N_TOK + r];
            float gw    = g_gw [e * N_TOK + r];
            float* orow = out + (size_t)token * H_DIM + col0 + tx * TN;
#pragma unroll
            for (int j = 0; j < TN; j++) {
                float v = acc[i][j] + b2[e * H_DIM + col0 + tx * TN + j];
                atomicAdd(&orow[j], gw * v);
            }
        }
    }
}

extern "C" void kernel_launch(void* const* d_in, const int* in_sizes, int n_in,
                              void* d_out, int out_size) {
    const float* x  = (const float*)d_in[0];
    const float* W1 = (const float*)d_in[1];
    const float* b1 = (const float*)d_in[2];
    const float* W2 = (const float*)d_in[3];
    const float* b2 = (const float*)d_in[4];
    const float* Wg = (const float*)d_in[5];
    const float* bg = (const float*)d_in[6];
    float* out = (float*)d_out;

    zero_kernel<<<1024, 256>>>(out, out_size);
    gate_kernel<<<N_TOK / 8, 256>>>(x, Wg, bg);
    offsets_kernel<<<1, 1>>>();
    ffn1_kernel<<<dim3(F_DIM / BN, N_EXP * TILES_PER_E), NTHREADS>>>(x, W1, b1);
    ffn2_kernel<<<dim3(H_DIM / BN, N_EXP * TILES_PER_E), NTHREADS>>>(W2, b2, out);
}

// round 2
// speedup vs baseline: 3.2786x; 3.2786x over previous
#include <cuda_runtime.h>
#include <math.h>
#include <stdint.h>

#define N_TOK 4096
#define H_DIM 1024
#define F_DIM 4096
#define N_EXP 8

#define BM 128
#define BN 128
#define BK 32
#define NTHREADS 256
#define TILES_PER_E (N_TOK / BM)  // 32

#define AS_STRIDE 40    // BK + 8 -> bank(8*gid+tig) all distinct, 16B-aligned rows
#define BS_STRIDE 136   // BN + 8 -> bank(8*tig+gid) all distinct, 16B-aligned rows

// Routing state + h scratch (allocation-free: __device__ globals).
__device__ int   g_cnt[N_EXP];
__device__ int   g_off[N_EXP];
__device__ int   g_tok[N_EXP * N_TOK];
__device__ float g_gw [N_EXP * N_TOK];
__device__ float g_h[(size_t)9216 * F_DIM];

__device__ __forceinline__ uint32_t f2tf32(float f) {
    uint32_t r;
    asm("cvt.rna.tf32.f32 %0, %1;" : "=r"(r) : "f"(f));
    return r;
}

__device__ __forceinline__ void mma_tf32(float c[4],
                                         uint32_t a0, uint32_t a1, uint32_t a2, uint32_t a3,
                                         uint32_t b0, uint32_t b1) {
    asm volatile(
        "mma.sync.aligned.m16n8k8.row.col.f32.tf32.tf32.f32 "
        "{%0,%1,%2,%3}, {%4,%5,%6,%7}, {%8,%9}, {%0,%1,%2,%3};\n"
        : "+f"(c[0]), "+f"(c[1]), "+f"(c[2]), "+f"(c[3])
        : "r"(a0), "r"(a1), "r"(a2), "r"(a3), "r"(b0), "r"(b1));
}

__global__ void zero_kernel(float* __restrict__ out, int n) {
    int i = blockIdx.x * blockDim.x + threadIdx.x;
    if (i < N_EXP) g_cnt[i] = 0;
    int stride = gridDim.x * blockDim.x;
    for (int j = i; j < n; j += stride) out[j] = 0.0f;
}

__global__ void gate_kernel(const float* __restrict__ x,
                            const float* __restrict__ Wg,
                            const float* __restrict__ bg) {
    int warp = threadIdx.x >> 5;
    int lane = threadIdx.x & 31;
    int n = blockIdx.x * (blockDim.x >> 5) + warp;
    if (n >= N_TOK) return;

    float acc[N_EXP];
#pragma unroll
    for (int e = 0; e < N_EXP; e++) acc[e] = 0.0f;

    const float* xr = x + (size_t)n * H_DIM;
    for (int h = lane; h < H_DIM; h += 32) {
        float xv = xr[h];
        const float4 w0 = *reinterpret_cast<const float4*>(Wg + h * N_EXP);
        const float4 w1 = *reinterpret_cast<const float4*>(Wg + h * N_EXP + 4);
        acc[0] += xv * w0.x; acc[1] += xv * w0.y;
        acc[2] += xv * w0.z; acc[3] += xv * w0.w;
        acc[4] += xv * w1.x; acc[5] += xv * w1.y;
        acc[6] += xv * w1.z; acc[7] += xv * w1.w;
    }
#pragma unroll
    for (int e = 0; e < N_EXP; e++) {
#pragma unroll
        for (int o = 16; o > 0; o >>= 1)
            acc[e] += __shfl_xor_sync(0xffffffffu, acc[e], o);
    }

    if (lane == 0) {
        float lg[N_EXP];
        float m = -1e30f;
#pragma unroll
        for (int e = 0; e < N_EXP; e++) {
            lg[e] = acc[e] + bg[e];
            m = fmaxf(m, lg[e]);
        }
        float s = 0.0f;
        float p[N_EXP];
#pragma unroll
        for (int e = 0; e < N_EXP; e++) { p[e] = expf(lg[e] - m); s += p[e]; }
        float inv = 1.0f / s;
#pragma unroll
        for (int e = 0; e < N_EXP; e++) p[e] *= inv;

        int i0 = 0;
#pragma unroll
        for (int e = 1; e < N_EXP; e++) if (p[e] > p[i0]) i0 = e;
        int i1 = (i0 == 0) ? 1 : 0;
#pragma unroll
        for (int e = 0; e < N_EXP; e++)
            if (e != i0 && p[e] > p[i1]) i1 = e;

        int pos0 = atomicAdd(&g_cnt[i0], 1);
        g_tok[i0 * N_TOK + pos0] = n;
        g_gw [i0 * N_TOK + pos0] = p[i0];
        int pos1 = atomicAdd(&g_cnt[i1], 1);
        g_tok[i1 * N_TOK + pos1] = n;
        g_gw [i1 * N_TOK + pos1] = p[i1];
    }
}

__global__ void offsets_kernel() {
    if (threadIdx.x == 0 && blockIdx.x == 0) {
        int off = 0;
        for (int e = 0; e < N_EXP; e++) {
            g_off[e] = off;
            off += ((g_cnt[e] + BM - 1) / BM) * BM;
        }
    }
}

// ---------------------------------------------------------------------------
// ffn1: h = gelu(X_gathered @ W1[e] + b1[e]) -> g_h   (K = H_DIM)
// ---------------------------------------------------------------------------
__global__ __launch_bounds__(NTHREADS) void ffn1_kernel(
    const float* __restrict__ x,
    const float* __restrict__ W1,
    const float* __restrict__ b1) {
    int e    = blockIdx.y / TILES_PER_E;
    int tile = blockIdx.y % TILES_PER_E;
    int row0 = tile * BM;
    int cnt  = g_cnt[e];
    if (row0 >= cnt) return;
    int off  = g_off[e];
    int col0 = blockIdx.x * BN;
    const float* B = W1 + (size_t)e * H_DIM * F_DIM;

    __shared__ uint32_t As[BM * AS_STRIDE];
    __shared__ uint32_t Bs[BK * BS_STRIDE];
    __shared__ int toks[BM];

    int tid = threadIdx.x;
    if (tid < BM) {
        int r = row0 + tid;
        if (r >= cnt) r = cnt - 1;
        toks[tid] = g_tok[e * N_TOK + r];
    }
    __syncthreads();

    int warp = tid >> 5, lane = tid & 31;
    int gid = lane >> 2, tig = lane & 3;
    int wm = (warp >> 2) * 64, wn = (warp & 3) * 32;

    float acc[4][4][4];
#pragma unroll
    for (int mf = 0; mf < 4; mf++)
#pragma unroll
        for (int nf = 0; nf < 4; nf++)
#pragma unroll
            for (int r = 0; r < 4; r++) acc[mf][nf][r] = 0.0f;

    int a_r = tid >> 3, a_c = (tid & 7) * 4;     // A f4 slots: rows a_r+32i
    int b_r = tid >> 5, b_c = (tid & 31) * 4;    // B f4 slots: rows b_r+8i

    float4 rA[4], rB[4];

    // prefetch k-tile 0
#pragma unroll
    for (int i = 0; i < 4; i++) {
        rA[i] = *reinterpret_cast<const float4*>(x + (size_t)toks[a_r + i * 32] * H_DIM + a_c);
        rB[i] = *reinterpret_cast<const float4*>(B + (size_t)(b_r + i * 8) * F_DIM + col0 + b_c);
    }
#pragma unroll
    for (int i = 0; i < 4; i++) {
        uint4 va = {f2tf32(rA[i].x), f2tf32(rA[i].y), f2tf32(rA[i].z), f2tf32(rA[i].w)};
        *reinterpret_cast<uint4*>(&As[(a_r + i * 32) * AS_STRIDE + a_c]) = va;
        uint4 vb = {f2tf32(rB[i].x), f2tf32(rB[i].y), f2tf32(rB[i].z), f2tf32(rB[i].w)};
        *reinterpret_cast<uint4*>(&Bs[(b_r + i * 8) * BS_STRIDE + b_c]) = vb;
    }
    __syncthreads();

    const int NKT = H_DIM / BK;
    for (int kt = 0; kt < NKT; kt++) {
        bool more = (kt + 1 < NKT);
        if (more) {
            int k0 = (kt + 1) * BK;
#pragma unroll
            for (int i = 0; i < 4; i++) {
                rA[i] = *reinterpret_cast<const float4*>(x + (size_t)toks[a_r + i * 32] * H_DIM + k0 + a_c);
                rB[i] = *reinterpret_cast<const float4*>(B + (size_t)(k0 + b_r + i * 8) * F_DIM + col0 + b_c);
            }
        }
#pragma unroll
        for (int ks = 0; ks < 4; ks++) {
            int k = ks * 8;
            uint32_t af[4][4], bf[4][2];
#pragma unroll
            for (int mf = 0; mf < 4; mf++) {
                int m = wm + mf * 16 + gid;
                af[mf][0] = As[m * AS_STRIDE + k + tig];
                af[mf][1] = As[(m + 8) * AS_STRIDE + k + tig];
                af[mf][2] = As[m * AS_STRIDE + k + tig + 4];
                af[mf][3] = As[(m + 8) * AS_STRIDE + k + tig + 4];
            }
#pragma unroll
            for (int nf = 0; nf < 4; nf++) {
                int n = wn + nf * 8 + gid;
                bf[nf][0] = Bs[(k + tig) * BS_STRIDE + n];
                bf[nf][1] = Bs[(k + tig + 4) * BS_STRIDE + n];
            }
#pragma unroll
            for (int mf = 0; mf < 4; mf++)
#pragma unroll
                for (int nf = 0; nf < 4; nf++)
                    mma_tf32(acc[mf][nf], af[mf][0], af[mf][1], af[mf][2], af[mf][3],
                             bf[nf][0], bf[nf][1]);
        }
        if (more) {
            __syncthreads();
#pragma unroll
            for (int i = 0; i < 4; i++) {
                uint4 va = {f2tf32(rA[i].x), f2tf32(rA[i].y), f2tf32(rA[i].z), f2tf32(rA[i].w)};
                *reinterpret_cast<uint4*>(&As[(a_r + i * 32) * AS_STRIDE + a_c]) = va;
                uint4 vb = {f2tf32(rB[i].x), f2tf32(rB[i].y), f2tf32(rB[i].z), f2tf32(rB[i].w)};
                *reinterpret_cast<uint4*>(&Bs[(b_r + i * 8) * BS_STRIDE + b_c]) = vb;
            }
            __syncthreads();
        }
    }

    // epilogue: bias + exact gelu -> g_h
#pragma unroll
    for (int mf = 0; mf < 4; mf++) {
#pragma unroll
        for (int r2 = 0; r2 < 2; r2++) {
            int m = wm + mf * 16 + gid + r2 * 8;
            float* hrow = g_h + (size_t)(off + row0 + m) * F_DIM + col0;
#pragma unroll
            for (int nf = 0; nf < 4; nf++) {
                int c = wn + nf * 8 + tig * 2;
                float v0 = acc[mf][nf][r2 * 2 + 0] + b1[e * F_DIM + col0 + c];
                float v1 = acc[mf][nf][r2 * 2 + 1] + b1[e * F_DIM + col0 + c + 1];
                float2 g;
                g.x = 0.5f * v0 * (1.0f + erff(v0 * 0.70710678118654752f));
                g.y = 0.5f * v1 * (1.0f + erff(v1 * 0.70710678118654752f));
                *reinterpret_cast<float2*>(hrow + c) = g;
            }
        }
    }
}

// ---------------------------------------------------------------------------
// ffn2: out[token] += gw * (h @ W2[e] + b2[e])   (K = F_DIM)
// ---------------------------------------------------------------------------
__global__ __launch_bounds__(NTHREADS) void ffn2_kernel(
    const float* __restrict__ W2,
    const float* __restrict__ b2,
    float* __restrict__ out) {
    int e    = blockIdx.y / TILES_PER_E;
    int tile = blockIdx.y % TILES_PER_E;
    int row0 = tile * BM;
    int cnt  = g_cnt[e];
    if (row0 >= cnt) return;
    int off  = g_off[e];
    int col0 = blockIdx.x * BN;
    const float* B = W2 + (size_t)e * F_DIM * H_DIM;
    const float* A = g_h + (size_t)(off + row0) * F_DIM;

    __shared__ uint32_t As[BM * AS_STRIDE];
    __shared__ uint32_t Bs[BK * BS_STRIDE];

    int tid = threadIdx.x;
    int warp = tid >> 5, lane = tid & 31;
    int gid = lane >> 2, tig = lane & 3;
    int wm = (warp >> 2) * 64, wn = (warp & 3) * 32;

    float acc[4][4][4];
#pragma unroll
    for (int mf = 0; mf < 4; mf++)
#pragma unroll
        for (int nf = 0; nf < 4; nf++)
#pragma unroll
            for (int r = 0; r < 4; r++) acc[mf][nf][r] = 0.0f;

    int a_r = tid >> 3, a_c = (tid & 7) * 4;
    int b_r = tid >> 5, b_c = (tid & 31) * 4;

    float4 rA[4], rB[4];

#pragma unroll
    for (int i = 0; i < 4; i++) {
        rA[i] = *reinterpret_cast<const float4*>(A + (size_t)(a_r + i * 32) * F_DIM + a_c);
        rB[i] = *reinterpret_cast<const float4*>(B + (size_t)(b_r + i * 8) * H_DIM + col0 + b_c);
    }
#pragma unroll
    for (int i = 0; i < 4; i++) {
        uint4 va = {f2tf32(rA[i].x), f2tf32(rA[i].y), f2tf32(rA[i].z), f2tf32(rA[i].w)};
        *reinterpret_cast<uint4*>(&As[(a_r + i * 32) * AS_STRIDE + a_c]) = va;
        uint4 vb = {f2tf32(rB[i].x), f2tf32(rB[i].y), f2tf32(rB[i].z), f2tf32(rB[i].w)};
        *reinterpret_cast<uint4*>(&Bs[(b_r + i * 8) * BS_STRIDE + b_c]) = vb;
    }
    __syncthreads();

    const int NKT = F_DIM / BK;
    for (int kt = 0; kt < NKT; kt++) {
        bool more = (kt + 1 < NKT);
        if (more) {
            int k0 = (kt + 1) * BK;
#pragma unroll
            for (int i = 0; i < 4; i++) {
                rA[i] = *reinterpret_cast<const float4*>(A + (size_t)(a_r + i * 32) * F_DIM + k0 + a_c);
                rB[i] = *reinterpret_cast<const float4*>(B + (size_t)(k0 + b_r + i * 8) * H_DIM + col0 + b_c);
            }
        }
#pragma unroll
        for (int ks = 0; ks < 4; ks++) {
            int k = ks * 8;
            uint32_t af[4][4], bf[4][2];
#pragma unroll
            for (int mf = 0; mf < 4; mf++) {
                int m = wm + mf * 16 + gid;
                af[mf][0] = As[m * AS_STRIDE + k + tig];
                af[mf][1] = As[(m + 8) * AS_STRIDE + k + tig];
                af[mf][2] = As[m * AS_STRIDE + k + tig + 4];
                af[mf][3] = As[(m + 8) * AS_STRIDE + k + tig + 4];
            }
#pragma unroll
            for (int nf = 0; nf < 4; nf++) {
                int n = wn + nf * 8 + gid;
                bf[nf][0] = Bs[(k + tig) * BS_STRIDE + n];
                bf[nf][1] = Bs[(k + tig + 4) * BS_STRIDE + n];
            }
#pragma unroll
            for (int mf = 0; mf < 4; mf++)
#pragma unroll
                for (int nf = 0; nf < 4; nf++)
                    mma_tf32(acc[mf][nf], af[mf][0], af[mf][1], af[mf][2], af[mf][3],
                             bf[nf][0], bf[nf][1]);
        }
        if (more) {
            __syncthreads();
#pragma unroll
            for (int i = 0; i < 4; i++) {
                uint4 va = {f2tf32(rA[i].x), f2tf32(rA[i].y), f2tf32(rA[i].z), f2tf32(rA[i].w)};
                *reinterpret_cast<uint4*>(&As[(a_r + i * 32) * AS_STRIDE + a_c]) = va;
                uint4 vb = {f2tf32(rB[i].x), f2tf32(rB[i].y), f2tf32(rB[i].z), f2tf32(rB[i].w)};
                *reinterpret_cast<uint4*>(&Bs[(b_r + i * 8) * BS_STRIDE + b_c]) = vb;
            }
            __syncthreads();
        }
    }

    // epilogue: bias, gate weight, atomic scatter
#pragma unroll
    for (int mf = 0; mf < 4; mf++) {
#pragma unroll
        for (int r2 = 0; r2 < 2; r2++) {
            int m = wm + mf * 16 + gid + r2 * 8;
            int r = row0 + m;
            if (r < cnt) {
                int   token = g_tok[e * N_TOK + r];
                float gw    = g_gw [e * N_TOK + r];
                float* orow = out + (size_t)token * H_DIM + col0;
#pragma unroll
                for (int nf = 0; nf < 4; nf++) {
                    int c = wn + nf * 8 + tig * 2;
                    float v0 = acc[mf][nf][r2 * 2 + 0] + b2[e * H_DIM + col0 + c];
                    float v1 = acc[mf][nf][r2 * 2 + 1] + b2[e * H_DIM + col0 + c + 1];
                    atomicAdd(orow + c,     gw * v0);
                    atomicAdd(orow + c + 1, gw * v1);
                }
            }
        }
    }
}

extern "C" void kernel_launch(void* const* d_in, const int* in_sizes, int n_in,
                              void* d_out, int out_size) {
    const float* x  = (const float*)d_in[0];
    const float* W1 = (const float*)d_in[1];
    const float* b1 = (const float*)d_in[2];
    const float* W2 = (const float*)d_in[3];
    const float* b2 = (const float*)d_in[4];
    const float* Wg = (const float*)d_in[5];
    const float* bg = (const float*)d_in[6];
    float* out = (float*)d_out;

    zero_kernel<<<1024, 256>>>(out, out_size);
    gate_kernel<<<N_TOK / 8, 256>>>(x, Wg, bg);
    offsets_kernel<<<1, 1>>>();
    ffn1_kernel<<<dim3(F_DIM / BN, N_EXP * TILES_PER_E), NTHREADS>>>(x, W1, b1);
    ffn2_kernel<<<dim3(H_DIM / BN, N_EXP * TILES_PER_E), NTHREADS>>>(W2, b2, out);
}